// round 1
// baseline (speedup 1.0000x reference)
#include <cuda_runtime.h>
#include <math.h>

#define Bn 32
#define Sn 256
#define Hn 4
#define Dn 64
#define Ln 1024
#define Fn 128

// Scratch (device globals are the allowed scratch mechanism)
__device__ float g_ux[Bn*Sn*Hn*Dn];     // mobius_matvec(U, we)  [B,S,H,D]
__device__ float g_uxn2[Bn*Sn*Hn];      // ||ux||^2
__device__ float g_enc[Bn*Sn*Hn*Dn];    // RNN states            [B,S,H,D]
__device__ float g_inter[Bn*Ln*Sn];     // sum_h dist            [B,L,S]

__device__ __forceinline__ float warp_sum(float v){
  #pragma unroll
  for (int o = 16; o > 0; o >>= 1) v += __shfl_xor_sync(0xffffffffu, v, o);
  return v;
}

// Warp-collective mobius_matvec: Wt is transposed [j][i] with row stride 66,
// xs is the input vector (64 floats in shared). Lane owns rows 2*lane, 2*lane+1.
__device__ __forceinline__ void warp_mmv(const float* Wt, const float* xs, int lane,
                                         float& r0, float& r1, float& sc_out){
  float a0 = 0.f, a1 = 0.f, xn2 = 0.f;
  #pragma unroll
  for (int j = 0; j < 64; j++){
    float xv = xs[j];
    float2 w = *(const float2*)(Wt + j*66 + 2*lane);
    a0  = fmaf(w.x, xv, a0);
    a1  = fmaf(w.y, xv, a1);
    xn2 = fmaf(xv, xv, xn2);       // redundant across lanes -> no reduction needed
  }
  float mn2 = warp_sum(fmaf(a0, a0, a1*a1));
  float xn = fmaxf(sqrtf(xn2), 1e-15f);
  float mn = fmaxf(sqrtf(mn2), 1e-15f);
  float sc = tanhf(mn / xn * atanhf(fminf(xn, 1.0f - 1e-7f)));
  float inv = sc / mn;             // scale * mx / mx_norm
  r0 = a0 * inv;
  r1 = a1 * inv;
  sc_out = sc;                     // == ||result||
}

// ---------------- Kernel A: gather + ux = mobius_matvec(U, we) ----------------
// grid = 32 b * 4 h * 8 s-chunks = 1024 blocks of 1 warp
__global__ void kernelA(const int* __restrict__ x,
                        const float* __restrict__ we,
                        const float* __restrict__ U){
  __shared__ float Ut[64*66];
  __shared__ float xs[64];
  int lane = threadIdx.x;
  int blk = blockIdx.x;
  int chunk = blk & 7;
  int h = (blk >> 3) & 3;
  int b = blk >> 5;
  const float* Ug = U + h*64*64;
  #pragma unroll 4
  for (int i = 0; i < 64; i++){
    Ut[lane*66 + i]      = Ug[i*64 + lane];
    Ut[(lane+32)*66 + i] = Ug[i*64 + lane + 32];
  }
  __syncwarp();
  for (int s = chunk*32; s < chunk*32 + 32; s++){
    int xv = x[b*Sn + s];
    float2 wv = *(const float2*)(we + ((size_t)xv*Hn + h)*Dn + 2*lane);
    __syncwarp();
    xs[2*lane]   = wv.x;
    xs[2*lane+1] = wv.y;
    __syncwarp();
    float r0, r1, sc;
    warp_mmv(Ut, xs, lane, r0, r1, sc);
    int base = ((b*Sn + s)*Hn + h)*Dn;
    *(float2*)(g_ux + base + 2*lane) = make_float2(r0, r1);
    if (lane == 0) g_uxn2[(b*Sn + s)*Hn + h] = sc*sc;
  }
}

// ---------------- Kernel B: the sequential hyper-RNN scan ----------------
// grid = 128 blocks (b,h) of 1 warp each; 256 dependent steps.
__global__ void kernelB(const float* __restrict__ W,
                        const float* __restrict__ bvec){
  __shared__ float Wt[64*66];
  __shared__ float hs[64];
  int lane = threadIdx.x;
  int blk = blockIdx.x;
  int h = blk & 3;
  int b = blk >> 2;
  const float* Wg = W + h*64*64;
  #pragma unroll 4
  for (int i = 0; i < 64; i++){
    Wt[lane*66 + i]      = Wg[i*64 + lane];
    Wt[(lane+32)*66 + i] = Wg[i*64 + lane + 32];
  }
  float bv0 = bvec[h*Dn + 2*lane];
  float bv1 = bvec[h*Dn + 2*lane + 1];
  float bn2 = warp_sum(fmaf(bv0, bv0, bv1*bv1));
  hs[2*lane] = 0.f; hs[2*lane+1] = 0.f;
  __syncwarp();
  int ubase = b*Sn*Hn*Dn + h*Dn + 2*lane;   // + t*256
  int nbase = b*Sn*Hn + h;                  // + t*4
  for (int t = 0; t < Sn; t++){
    // prefetch ux for this step (latency hidden under the matvec)
    float2 ux = *(const float2*)(g_ux + ubase + t*(Hn*Dn));
    float uy2 = g_uxn2[nbase + t*Hn];
    float w0, w1, sw;
    warp_mmv(Wt, hs, lane, w0, w1, sw);     // wh = mobius_matvec(W, h)
    float x2 = sw*sw;
    // mobius_add(wh, ux)
    float xy = warp_sum(fmaf(w0, ux.x, w1*ux.y));
    float den = fmaxf(1.0f + 2.0f*xy + x2*uy2, 1e-15f);
    float cx = (1.0f + 2.0f*xy + uy2) / den;
    float cy = (1.0f - x2) / den;
    float A0 = fmaf(cx, w0, cy*ux.x);
    float A1 = fmaf(cx, w1, cy*ux.y);
    // mobius_add(A, b): need ||A||^2 and A.b (paired reduction)
    float an2 = fmaf(A0, A0, A1*A1);
    float ab  = fmaf(A0, bv0, A1*bv1);
    #pragma unroll
    for (int o = 16; o > 0; o >>= 1){
      an2 += __shfl_xor_sync(0xffffffffu, an2, o);
      ab  += __shfl_xor_sync(0xffffffffu, ab,  o);
    }
    float den2 = fmaxf(1.0f + 2.0f*ab + an2*bn2, 1e-15f);
    float c2x = (1.0f + 2.0f*ab + bn2) / den2;
    float c2y = (1.0f - an2) / den2;
    float n0 = fmaf(c2x, A0, c2y*bv0);
    float n1 = fmaf(c2x, A1, c2y*bv1);
    __syncwarp();
    hs[2*lane] = n0; hs[2*lane+1] = n1;
    __syncwarp();
    *(float2*)(g_enc + ubase + t*(Hn*Dn)) = make_float2(n0, n1);
  }
}

// ---------------- Kernel C: poincare dist to all labels, summed over h ----------------
// grid = 32 b * 32 l-tiles = 1024 blocks, 256 threads, dynamic smem.
// Block: 32 labels, loop s in chunks of 64. Thread tile: 2 l x 4 s.
#define LSTR 260
__global__ void kernelC(const float* __restrict__ lab){
  extern __shared__ float smem[];
  float* lab_sh = smem;                    // 32*260
  float* enc_sh = smem + 32*LSTR;          // 64*260
  float* lb2i   = smem + 32*LSTR + 64*LSTR; // 32*4*2
  float* asn    = lb2i + 256;              // 64*4*2
  int t = threadIdx.x;
  int b  = blockIdx.x >> 5;
  int l0 = (blockIdx.x & 31) << 5;

  for (int idx = t; idx < 32*256; idx += 256){
    int li = idx >> 8, c = idx & 255;
    lab_sh[li*LSTR + c] = lab[(l0 + li)*(Hn*Dn) + c];
  }
  __syncthreads();
  if (t < 128){
    int li = t >> 2, hh = t & 3;
    const float* p = lab_sh + li*LSTR + hh*Dn;
    float s2 = 0.f;
    #pragma unroll
    for (int d = 0; d < 64; d++) s2 = fmaf(p[d], p[d], s2);
    lb2i[t*2]   = s2;
    lb2i[t*2+1] = 1.0f / fmaxf(1.0f - s2, 1e-15f);
  }
  __syncthreads();

  int li = t & 15, si = t >> 4;
  for (int c4 = 0; c4 < 4; c4++){
    int s0 = c4 * 64;
    for (int idx = t; idx < 64*256; idx += 256){
      int ss = idx >> 8, c = idx & 255;
      enc_sh[ss*LSTR + c] = g_enc[(b*Sn + s0 + ss)*(Hn*Dn) + c];
    }
    __syncthreads();
    {
      int ss = t >> 2, hh = t & 3;
      const float* p = enc_sh + ss*LSTR + hh*Dn;
      float s2 = 0.f;
      #pragma unroll
      for (int d = 0; d < 64; d++) s2 = fmaf(p[d], p[d], s2);
      asn[t*2]   = s2;
      asn[t*2+1] = 1.0f / fmaxf(1.0f - s2, 1e-15f);
    }
    __syncthreads();

    float ds[2][4] = {{0.f,0.f,0.f,0.f},{0.f,0.f,0.f,0.f}};
    #pragma unroll
    for (int hh = 0; hh < 4; hh++){
      float acc[2][4] = {{0.f,0.f,0.f,0.f},{0.f,0.f,0.f,0.f}};
      const float* lp0 = lab_sh + li*LSTR + hh*Dn;
      const float* lp1 = lp0 + 16*LSTR;
      const float* ep  = enc_sh + si*LSTR + hh*Dn;
      #pragma unroll
      for (int d4 = 0; d4 < 16; d4++){
        float4 la0 = *(const float4*)(lp0 + 4*d4);
        float4 la1 = *(const float4*)(lp1 + 4*d4);
        float4 e0 = *(const float4*)(ep + 4*d4);
        float4 e1 = *(const float4*)(ep + 16*LSTR + 4*d4);
        float4 e2 = *(const float4*)(ep + 32*LSTR + 4*d4);
        float4 e3 = *(const float4*)(ep + 48*LSTR + 4*d4);
        acc[0][0] = fmaf(la0.x,e0.x,fmaf(la0.y,e0.y,fmaf(la0.z,e0.z,fmaf(la0.w,e0.w,acc[0][0]))));
        acc[0][1] = fmaf(la0.x,e1.x,fmaf(la0.y,e1.y,fmaf(la0.z,e1.z,fmaf(la0.w,e1.w,acc[0][1]))));
        acc[0][2] = fmaf(la0.x,e2.x,fmaf(la0.y,e2.y,fmaf(la0.z,e2.z,fmaf(la0.w,e2.w,acc[0][2]))));
        acc[0][3] = fmaf(la0.x,e3.x,fmaf(la0.y,e3.y,fmaf(la0.z,e3.z,fmaf(la0.w,e3.w,acc[0][3]))));
        acc[1][0] = fmaf(la1.x,e0.x,fmaf(la1.y,e0.y,fmaf(la1.z,e0.z,fmaf(la1.w,e0.w,acc[1][0]))));
        acc[1][1] = fmaf(la1.x,e1.x,fmaf(la1.y,e1.y,fmaf(la1.z,e1.z,fmaf(la1.w,e1.w,acc[1][1]))));
        acc[1][2] = fmaf(la1.x,e2.x,fmaf(la1.y,e2.y,fmaf(la1.z,e2.z,fmaf(la1.w,e2.w,acc[1][2]))));
        acc[1][3] = fmaf(la1.x,e3.x,fmaf(la1.y,e3.y,fmaf(la1.z,e3.z,fmaf(la1.w,e3.w,acc[1][3]))));
      }
      #pragma unroll
      for (int a = 0; a < 2; a++){
        float lb2 = lb2i[((li + a*16)*4 + hh)*2];
        float ilb = lb2i[((li + a*16)*4 + hh)*2 + 1];
        #pragma unroll
        for (int q = 0; q < 4; q++){
          float av = asn[((si + q*16)*4 + hh)*2];
          float ia = asn[((si + q*16)*4 + hh)*2 + 1];
          float c2 = fmaxf(av + lb2 - 2.0f*acc[a][q], 0.0f);
          float tt = fmaxf(2.0f*c2*ia*ilb, 1e-7f);   // = arg - 1
          float prod = fmaf(tt, tt, 2.0f*tt);        // tt*(tt+2) = arg^2 - 1
          float sq;
          asm("sqrt.approx.f32 %0, %1;" : "=f"(sq) : "f"(prod));
          ds[a][q] += __logf(1.0f + tt + sq);        // arccosh(arg)
        }
      }
    }
    #pragma unroll
    for (int a = 0; a < 2; a++)
      #pragma unroll
      for (int q = 0; q < 4; q++)
        g_inter[(b*Ln + l0 + li + a*16)*Sn + s0 + si + q*16] = ds[a][q];
    __syncthreads();
  }
}

// ---------------- Kernel D: MLP  out[b,l] = w2 . relu(w1 @ inter + b1) + b2 ----------------
// GEMM [32768 x 256] * [256 x 128], fused relu + f-reduction. 512 blocks x 256 thr.
__global__ void kernelD(const float* __restrict__ w1, const float* __restrict__ b1,
                        const float* __restrict__ w2, const float* __restrict__ b2,
                        float* __restrict__ out){
  __shared__ float As[64*36];
  __shared__ float Bs[32*132];
  int t = threadIdx.x;
  int lane = t & 31;
  int r0 = blockIdx.x * 64;
  int rg = t >> 4, cg = t & 15;
  float acc[4][8];
  #pragma unroll
  for (int i = 0; i < 4; i++)
    #pragma unroll
    for (int j = 0; j < 8; j++) acc[i][j] = 0.f;

  for (int kc = 0; kc < 8; kc++){
    int s0 = kc * 32;
    #pragma unroll
    for (int it = 0; it < 8; it++){
      int ri = (t >> 5) + it*8;
      As[ri*36 + lane] = g_inter[(r0 + ri)*Sn + s0 + lane];
    }
    #pragma unroll
    for (int it = 0; it < 16; it++){
      int f = (t >> 5) + it*8;
      Bs[lane*132 + f] = w1[f*Sn + s0 + lane];
    }
    __syncthreads();
    #pragma unroll
    for (int k = 0; k < 32; k++){
      float av[4];
      #pragma unroll
      for (int i = 0; i < 4; i++) av[i] = As[(rg*4 + i)*36 + k];
      float4 bq0 = *(const float4*)(Bs + k*132 + cg*8);
      float4 bq1 = *(const float4*)(Bs + k*132 + cg*8 + 4);
      float bv[8] = {bq0.x,bq0.y,bq0.z,bq0.w,bq1.x,bq1.y,bq1.z,bq1.w};
      #pragma unroll
      for (int i = 0; i < 4; i++)
        #pragma unroll
        for (int j = 0; j < 8; j++)
          acc[i][j] = fmaf(av[i], bv[j], acc[i][j]);
    }
    __syncthreads();
  }
  float b1l[8], w2l[8];
  #pragma unroll
  for (int j = 0; j < 8; j++){
    int f = cg*8 + j;
    b1l[j] = b1[f];
    w2l[j] = w2[f];
  }
  float p[4];
  #pragma unroll
  for (int i = 0; i < 4; i++){
    float s = 0.f;
    #pragma unroll
    for (int j = 0; j < 8; j++)
      s = fmaf(fmaxf(acc[i][j] + b1l[j], 0.f), w2l[j], s);
    p[i] = s;
  }
  #pragma unroll
  for (int o = 1; o < 16; o <<= 1){
    #pragma unroll
    for (int i = 0; i < 4; i++) p[i] += __shfl_xor_sync(0xffffffffu, p[i], o);
  }
  if (cg == 0){
    float bb = b2[0];
    #pragma unroll
    for (int i = 0; i < 4; i++) out[r0 + rg*4 + i] = p[i] + bb;
  }
}

extern "C" void kernel_launch(void* const* d_in, const int* in_sizes, int n_in,
                              void* d_out, int out_size){
  const int*   x   = (const int*)  d_in[0];
  const float* we  = (const float*)d_in[1];
  const float* lab = (const float*)d_in[2];
  const float* W   = (const float*)d_in[3];
  const float* U   = (const float*)d_in[4];
  const float* bv  = (const float*)d_in[5];
  const float* w1  = (const float*)d_in[6];
  const float* b1  = (const float*)d_in[7];
  const float* w2  = (const float*)d_in[8];
  const float* b2  = (const float*)d_in[9];
  float* out = (float*)d_out;

  const int smemC = (32*LSTR + 64*LSTR + 256 + 512) * (int)sizeof(float);
  cudaFuncSetAttribute(kernelC, cudaFuncAttributeMaxDynamicSharedMemorySize, smemC);

  kernelA<<<1024, 32>>>(x, we, U);
  kernelB<<<128, 32>>>(W, bv);
  kernelC<<<1024, 256, smemC>>>(lab);
  kernelD<<<512, 256>>>(w1, b1, w2, b2, out);
}

// round 3
// speedup vs baseline: 1.0122x; 1.0122x over previous
#include <cuda_runtime.h>
#include <math.h>

#define Bn 32
#define Sn 256
#define Hn 4
#define Dn 64
#define Ln 1024
#define Fn 128

// Scratch (device globals are the allowed scratch mechanism)
__device__ float g_ux[Bn*Sn*Hn*Dn];     // mobius_matvec(U, we)  [B,S,H,D]
__device__ float g_uxn2[Bn*Sn*Hn];      // ||ux||^2
__device__ float g_enc[Bn*Sn*Hn*Dn];    // RNN states            [B,S,H,D]
__device__ float g_inter[Bn*Ln*Sn];     // sum_h dist            [B,L,S]

__device__ __forceinline__ float warp_sum(float v){
  #pragma unroll
  for (int o = 16; o > 0; o >>= 1) v += __shfl_xor_sync(0xffffffffu, v, o);
  return v;
}

// Warp-collective mobius_matvec: Wt is transposed [j][i] with row stride 66,
// xs is the input vector (64 floats in shared). Lane owns rows 2*lane, 2*lane+1.
__device__ __forceinline__ void warp_mmv(const float* Wt, const float* xs, int lane,
                                         float& r0, float& r1, float& sc_out){
  float a0 = 0.f, a1 = 0.f, xn2 = 0.f;
  #pragma unroll
  for (int j = 0; j < 64; j++){
    float xv = xs[j];
    float2 w = *(const float2*)(Wt + j*66 + 2*lane);
    a0  = fmaf(w.x, xv, a0);
    a1  = fmaf(w.y, xv, a1);
    xn2 = fmaf(xv, xv, xn2);       // redundant across lanes -> no reduction needed
  }
  float mn2 = warp_sum(fmaf(a0, a0, a1*a1));
  float xn = fmaxf(sqrtf(xn2), 1e-15f);
  float mn = fmaxf(sqrtf(mn2), 1e-15f);
  float sc = tanhf(mn / xn * atanhf(fminf(xn, 1.0f - 1e-7f)));
  float inv = sc / mn;             // scale * mx / mx_norm
  r0 = a0 * inv;
  r1 = a1 * inv;
  sc_out = sc;                     // == ||result||
}

// ---------------- Kernel A: gather + ux = mobius_matvec(U, we) ----------------
// grid = 32 b * 4 h * 8 s-chunks = 1024 blocks of 1 warp
__global__ void kernelA(const int* __restrict__ x,
                        const float* __restrict__ we,
                        const float* __restrict__ U){
  __shared__ float Ut[64*66];
  __shared__ float xs[64];
  int lane = threadIdx.x;
  int blk = blockIdx.x;
  int chunk = blk & 7;
  int h = (blk >> 3) & 3;
  int b = blk >> 5;
  const float* Ug = U + h*64*64;
  #pragma unroll 4
  for (int i = 0; i < 64; i++){
    Ut[lane*66 + i]      = Ug[i*64 + lane];
    Ut[(lane+32)*66 + i] = Ug[i*64 + lane + 32];
  }
  __syncwarp();
  for (int s = chunk*32; s < chunk*32 + 32; s++){
    int xv = x[b*Sn + s];
    float2 wv = *(const float2*)(we + ((size_t)xv*Hn + h)*Dn + 2*lane);
    __syncwarp();
    xs[2*lane]   = wv.x;
    xs[2*lane+1] = wv.y;
    __syncwarp();
    float r0, r1, sc;
    warp_mmv(Ut, xs, lane, r0, r1, sc);
    int base = ((b*Sn + s)*Hn + h)*Dn;
    *(float2*)(g_ux + base + 2*lane) = make_float2(r0, r1);
    if (lane == 0) g_uxn2[(b*Sn + s)*Hn + h] = sc*sc;
  }
}

// ---------------- Kernel B: the sequential hyper-RNN scan ----------------
// grid = 128 blocks (b,h) of 1 warp each; 256 dependent steps.
__global__ void kernelB(const float* __restrict__ W,
                        const float* __restrict__ bvec){
  __shared__ float Wt[64*66];
  __shared__ float hs[64];
  int lane = threadIdx.x;
  int blk = blockIdx.x;
  int h = blk & 3;
  int b = blk >> 2;
  const float* Wg = W + h*64*64;
  #pragma unroll 4
  for (int i = 0; i < 64; i++){
    Wt[lane*66 + i]      = Wg[i*64 + lane];
    Wt[(lane+32)*66 + i] = Wg[i*64 + lane + 32];
  }
  float bv0 = bvec[h*Dn + 2*lane];
  float bv1 = bvec[h*Dn + 2*lane + 1];
  float bn2 = warp_sum(fmaf(bv0, bv0, bv1*bv1));
  hs[2*lane] = 0.f; hs[2*lane+1] = 0.f;
  __syncwarp();
  int ubase = b*Sn*Hn*Dn + h*Dn + 2*lane;   // + t*256
  int nbase = b*Sn*Hn + h;                  // + t*4
  for (int t = 0; t < Sn; t++){
    // prefetch ux for this step (latency hidden under the matvec)
    float2 ux = *(const float2*)(g_ux + ubase + t*(Hn*Dn));
    float uy2 = g_uxn2[nbase + t*Hn];
    float w0, w1, sw;
    warp_mmv(Wt, hs, lane, w0, w1, sw);     // wh = mobius_matvec(W, h)
    float x2 = sw*sw;
    // mobius_add(wh, ux)
    float xy = warp_sum(fmaf(w0, ux.x, w1*ux.y));
    float den = fmaxf(1.0f + 2.0f*xy + x2*uy2, 1e-15f);
    float cx = (1.0f + 2.0f*xy + uy2) / den;
    float cy = (1.0f - x2) / den;
    float A0 = fmaf(cx, w0, cy*ux.x);
    float A1 = fmaf(cx, w1, cy*ux.y);
    // mobius_add(A, b): need ||A||^2 and A.b (paired reduction)
    float an2 = fmaf(A0, A0, A1*A1);
    float ab  = fmaf(A0, bv0, A1*bv1);
    #pragma unroll
    for (int o = 16; o > 0; o >>= 1){
      an2 += __shfl_xor_sync(0xffffffffu, an2, o);
      ab  += __shfl_xor_sync(0xffffffffu, ab,  o);
    }
    float den2 = fmaxf(1.0f + 2.0f*ab + an2*bn2, 1e-15f);
    float c2x = (1.0f + 2.0f*ab + bn2) / den2;
    float c2y = (1.0f - an2) / den2;
    float n0 = fmaf(c2x, A0, c2y*bv0);
    float n1 = fmaf(c2x, A1, c2y*bv1);
    __syncwarp();
    hs[2*lane] = n0; hs[2*lane+1] = n1;
    __syncwarp();
    *(float2*)(g_enc + ubase + t*(Hn*Dn)) = make_float2(n0, n1);
  }
}

// ---------------- Kernel C: poincare dist to all labels, summed over h ----------------
// grid = 32 b * 32 l-tiles = 1024 blocks, 256 threads, dynamic smem.
// Block: 32 labels, loop s in chunks of 64. Thread tile: 2 l x 4 s.
#define LSTR 260
__global__ void kernelC(const float* __restrict__ lab){
  extern __shared__ float smem[];
  float* lab_sh = smem;                    // 32*260
  float* enc_sh = smem + 32*LSTR;          // 64*260
  float* lb2i   = smem + 32*LSTR + 64*LSTR; // 32*4*2
  float* asn    = lb2i + 256;              // 64*4*2
  int t = threadIdx.x;
  int b  = blockIdx.x >> 5;
  int l0 = (blockIdx.x & 31) << 5;

  for (int idx = t; idx < 32*256; idx += 256){
    int li = idx >> 8, c = idx & 255;
    lab_sh[li*LSTR + c] = lab[(l0 + li)*(Hn*Dn) + c];
  }
  __syncthreads();
  if (t < 128){
    int li = t >> 2, hh = t & 3;
    const float* p = lab_sh + li*LSTR + hh*Dn;
    float s2 = 0.f;
    #pragma unroll
    for (int d = 0; d < 64; d++) s2 = fmaf(p[d], p[d], s2);
    lb2i[t*2]   = s2;
    lb2i[t*2+1] = 1.0f / fmaxf(1.0f - s2, 1e-15f);
  }
  __syncthreads();

  int li = t & 15, si = t >> 4;
  for (int c4 = 0; c4 < 4; c4++){
    int s0 = c4 * 64;
    for (int idx = t; idx < 64*256; idx += 256){
      int ss = idx >> 8, c = idx & 255;
      enc_sh[ss*LSTR + c] = g_enc[(b*Sn + s0 + ss)*(Hn*Dn) + c];
    }
    __syncthreads();
    {
      int ss = t >> 2, hh = t & 3;
      const float* p = enc_sh + ss*LSTR + hh*Dn;
      float s2 = 0.f;
      #pragma unroll
      for (int d = 0; d < 64; d++) s2 = fmaf(p[d], p[d], s2);
      asn[t*2]   = s2;
      asn[t*2+1] = 1.0f / fmaxf(1.0f - s2, 1e-15f);
    }
    __syncthreads();

    float ds[2][4] = {{0.f,0.f,0.f,0.f},{0.f,0.f,0.f,0.f}};
    #pragma unroll
    for (int hh = 0; hh < 4; hh++){
      float acc[2][4] = {{0.f,0.f,0.f,0.f},{0.f,0.f,0.f,0.f}};
      const float* lp0 = lab_sh + li*LSTR + hh*Dn;
      const float* lp1 = lp0 + 16*LSTR;
      const float* ep  = enc_sh + si*LSTR + hh*Dn;
      #pragma unroll
      for (int d4 = 0; d4 < 16; d4++){
        float4 la0 = *(const float4*)(lp0 + 4*d4);
        float4 la1 = *(const float4*)(lp1 + 4*d4);
        float4 e0 = *(const float4*)(ep + 4*d4);
        float4 e1 = *(const float4*)(ep + 16*LSTR + 4*d4);
        float4 e2 = *(const float4*)(ep + 32*LSTR + 4*d4);
        float4 e3 = *(const float4*)(ep + 48*LSTR + 4*d4);
        acc[0][0] = fmaf(la0.x,e0.x,fmaf(la0.y,e0.y,fmaf(la0.z,e0.z,fmaf(la0.w,e0.w,acc[0][0]))));
        acc[0][1] = fmaf(la0.x,e1.x,fmaf(la0.y,e1.y,fmaf(la0.z,e1.z,fmaf(la0.w,e1.w,acc[0][1]))));
        acc[0][2] = fmaf(la0.x,e2.x,fmaf(la0.y,e2.y,fmaf(la0.z,e2.z,fmaf(la0.w,e2.w,acc[0][2]))));
        acc[0][3] = fmaf(la0.x,e3.x,fmaf(la0.y,e3.y,fmaf(la0.z,e3.z,fmaf(la0.w,e3.w,acc[0][3]))));
        acc[1][0] = fmaf(la1.x,e0.x,fmaf(la1.y,e0.y,fmaf(la1.z,e0.z,fmaf(la1.w,e0.w,acc[1][0]))));
        acc[1][1] = fmaf(la1.x,e1.x,fmaf(la1.y,e1.y,fmaf(la1.z,e1.z,fmaf(la1.w,e1.w,acc[1][1]))));
        acc[1][2] = fmaf(la1.x,e2.x,fmaf(la1.y,e2.y,fmaf(la1.z,e2.z,fmaf(la1.w,e2.w,acc[1][2]))));
        acc[1][3] = fmaf(la1.x,e3.x,fmaf(la1.y,e3.y,fmaf(la1.z,e3.z,fmaf(la1.w,e3.w,acc[1][3]))));
      }
      #pragma unroll
      for (int a = 0; a < 2; a++){
        float lb2 = lb2i[((li + a*16)*4 + hh)*2];
        float ilb = lb2i[((li + a*16)*4 + hh)*2 + 1];
        #pragma unroll
        for (int q = 0; q < 4; q++){
          float av = asn[((si + q*16)*4 + hh)*2];
          float ia = asn[((si + q*16)*4 + hh)*2 + 1];
          float c2 = fmaxf(av + lb2 - 2.0f*acc[a][q], 0.0f);
          float tt = fmaxf(2.0f*c2*ia*ilb, 1e-7f);   // = arg - 1
          float prod = fmaf(tt, tt, 2.0f*tt);        // tt*(tt+2) = arg^2 - 1
          float sq;
          asm("sqrt.approx.f32 %0, %1;" : "=f"(sq) : "f"(prod));
          ds[a][q] += __logf(1.0f + tt + sq);        // arccosh(arg)
        }
      }
    }
    #pragma unroll
    for (int a = 0; a < 2; a++)
      #pragma unroll
      for (int q = 0; q < 4; q++)
        g_inter[(b*Ln + l0 + li + a*16)*Sn + s0 + si + q*16] = ds[a][q];
    __syncthreads();
  }
}

// ---------------- Kernel D: MLP  out[b,l] = w2 . relu(w1 @ inter + b1) + b2 ----------------
// GEMM [32768 x 256] * [256 x 128], fused relu + f-reduction. 512 blocks x 256 thr.
__global__ void kernelD(const float* __restrict__ w1, const float* __restrict__ b1,
                        const float* __restrict__ w2, const float* __restrict__ b2,
                        float* __restrict__ out){
  __shared__ float As[64*36];
  __shared__ float Bs[32*132];
  int t = threadIdx.x;
  int lane = t & 31;
  int r0 = blockIdx.x * 64;
  int rg = t >> 4, cg = t & 15;
  float acc[4][8];
  #pragma unroll
  for (int i = 0; i < 4; i++)
    #pragma unroll
    for (int j = 0; j < 8; j++) acc[i][j] = 0.f;

  for (int kc = 0; kc < 8; kc++){
    int s0 = kc * 32;
    #pragma unroll
    for (int it = 0; it < 8; it++){
      int ri = (t >> 5) + it*8;
      As[ri*36 + lane] = g_inter[(r0 + ri)*Sn + s0 + lane];
    }
    #pragma unroll
    for (int it = 0; it < 16; it++){
      int f = (t >> 5) + it*8;
      Bs[lane*132 + f] = w1[f*Sn + s0 + lane];
    }
    __syncthreads();
    #pragma unroll
    for (int k = 0; k < 32; k++){
      float av[4];
      #pragma unroll
      for (int i = 0; i < 4; i++) av[i] = As[(rg*4 + i)*36 + k];
      float4 bq0 = *(const float4*)(Bs + k*132 + cg*8);
      float4 bq1 = *(const float4*)(Bs + k*132 + cg*8 + 4);
      float bv[8] = {bq0.x,bq0.y,bq0.z,bq0.w,bq1.x,bq1.y,bq1.z,bq1.w};
      #pragma unroll
      for (int i = 0; i < 4; i++)
        #pragma unroll
        for (int j = 0; j < 8; j++)
          acc[i][j] = fmaf(av[i], bv[j], acc[i][j]);
    }
    __syncthreads();
  }
  float b1l[8], w2l[8];
  #pragma unroll
  for (int j = 0; j < 8; j++){
    int f = cg*8 + j;
    b1l[j] = b1[f];
    w2l[j] = w2[f];
  }
  float p[4];
  #pragma unroll
  for (int i = 0; i < 4; i++){
    float s = 0.f;
    #pragma unroll
    for (int j = 0; j < 8; j++)
      s = fmaf(fmaxf(acc[i][j] + b1l[j], 0.f), w2l[j], s);
    p[i] = s;
  }
  #pragma unroll
  for (int o = 1; o < 16; o <<= 1){
    #pragma unroll
    for (int i = 0; i < 4; i++) p[i] += __shfl_xor_sync(0xffffffffu, p[i], o);
  }
  if (cg == 0){
    float bb = b2[0];
    #pragma unroll
    for (int i = 0; i < 4; i++) out[r0 + rg*4 + i] = p[i] + bb;
  }
}

extern "C" void kernel_launch(void* const* d_in, const int* in_sizes, int n_in,
                              void* d_out, int out_size){
  const int*   x   = (const int*)  d_in[0];
  const float* we  = (const float*)d_in[1];
  const float* lab = (const float*)d_in[2];
  const float* W   = (const float*)d_in[3];
  const float* U   = (const float*)d_in[4];
  const float* bv  = (const float*)d_in[5];
  const float* w1  = (const float*)d_in[6];
  const float* b1  = (const float*)d_in[7];
  const float* w2  = (const float*)d_in[8];
  const float* b2  = (const float*)d_in[9];
  float* out = (float*)d_out;

  const int smemC = (32*LSTR + 64*LSTR + 256 + 512) * (int)sizeof(float);
  cudaFuncSetAttribute(kernelC, cudaFuncAttributeMaxDynamicSharedMemorySize, smemC);

  kernelA<<<1024, 32>>>(x, we, U);
  kernelB<<<128, 32>>>(W, bv);
  kernelC<<<1024, 256, smemC>>>(lab);
  kernelD<<<512, 256>>>(w1, b1, w2, b2, out);
}